// round 7
// baseline (speedup 1.0000x reference)
#include <cuda_runtime.h>
#include <cuda_fp16.h>
#include <cstdint>

// ============================================================================
// Problem constants (fixed shapes for SVMModel_19267223290147)
// ============================================================================
#define BB 2048      // batch rows
#define NN 32768     // train rows
#define DD 128       // feature dim
#define BT 128       // CTA B-tile (M)
#define NT 128       // CTA N-tile
#define NSPLITS 8    // N chunks across grid.x
#define BTILES  16   // B tiles across grid.y
#define NCHUNK (NN / NSPLITS)     // 4096
#define TILES  (NCHUNK / NT)      // 32
#define THREADS 512  // 16 warps: 4/SMSP for latency hiding
#define NBUF 3

// SMEM: A tile (32KB) + 3-deep B ring (96KB). Tiles stored as 2 chunks of
// [128 rows x 64 fp16 (128B)] SW128-swizzled.
#define SMEM_A 0
#define SMEM_B 32768
#define TILE_BYTES 32768
#define SMEM_TOTAL (SMEM_B + NBUF * TILE_BYTES)

#define SWZ(o) ((o) ^ (((o) >> 3) & 0x70))

// ============================================================================
// Device globals (static allocation: allowed)
// ============================================================================
__device__ __half g_xbf[BB * DD];              // x * (2*gamma*log2e) fp16
__device__ __half g_tbf[NN * DD];              // train_data fp16
__device__ float  g_c1[NN];                    // W[n] * exp(-g*t2[n])
__device__ float  g_ex[BB];                    // exp(-g*x2[b])
__device__ float  g_partial[NSPLITS * BB * 4]; // per (ns, b, warp_n quarter)
__device__ unsigned g_arr[BTILES];             // per-btile arrival counters (0-init)

// ============================================================================
// PTX helpers (sm_100 base-target safe)
// ============================================================================
__device__ __forceinline__ uint32_t smem_u32(const void* p) {
    uint32_t a;
    asm("{ .reg .u64 t; cvta.to.shared.u64 t, %1; cvt.u32.u64 %0, t; }" : "=r"(a) : "l"(p));
    return a;
}
__device__ __forceinline__ float ex2f(float x) {
    float y; asm("ex2.approx.f32 %0, %1;" : "=f"(y) : "f"(x)); return y;
}
__device__ __forceinline__ void cp_async16(uint32_t dst, const void* src) {
    asm volatile("cp.async.cg.shared.global [%0], [%1], 16;" :: "r"(dst), "l"(src));
}
#define CP_COMMIT() asm volatile("cp.async.commit_group;" ::: "memory")

__device__ __forceinline__ void ldsm4(uint32_t* r, uint32_t addr) {
    asm volatile("ldmatrix.sync.aligned.m8n8.x4.shared.b16 {%0,%1,%2,%3}, [%4];"
                 : "=r"(r[0]), "=r"(r[1]), "=r"(r[2]), "=r"(r[3]) : "r"(addr));
}
// volatile: bounds live ranges; cross-warp occupancy provides the overlap.
__device__ __forceinline__ void mma16816(float* c, const uint32_t* a, const uint32_t* b) {
    asm volatile(
        "mma.sync.aligned.m16n8k16.row.col.f32.f16.f16.f32 "
        "{%0,%1,%2,%3}, {%4,%5,%6,%7}, {%8,%9}, {%0,%1,%2,%3};"
        : "+f"(c[0]), "+f"(c[1]), "+f"(c[2]), "+f"(c[3])
        : "r"(a[0]), "r"(a[1]), "r"(a[2]), "r"(a[3]), "r"(b[0]), "r"(b[1]));
}

// cp.async one [128 x 128 fp16] tile into an SMEM ring slot (chunked SW128).
// 2048 16-byte pieces, 4 per thread (512 threads), coalesced in GMEM.
__device__ __forceinline__ void issue_tile(uint32_t sm_base, const __half* src) {
    int tid = threadIdx.x;
    #pragma unroll
    for (int it = 0; it < 4; it++) {
        int k = tid + it * 512;
        int row = k >> 4;
        int rem = k & 15;
        int c = rem >> 3;
        int j = rem & 7;
        uint32_t dst = sm_base + c * 16384 + SWZ((uint32_t)(row * 128 + j * 16));
        cp_async16(dst, src + row * 128 + c * 64 + j * 8);
    }
}

// ============================================================================
// Prep kernels (fp32 norms; x pre-scaled by 2*gamma*log2e)
// ============================================================================
__global__ void prep_x_kernel(const float* __restrict__ x, const float* __restrict__ gamma) {
    int w = (blockIdx.x * blockDim.x + threadIdx.x) >> 5;
    int lane = threadIdx.x & 31;
    if (w >= BB) return;
    float gm = gamma[0];
    float s = 2.0f * gm * 1.4426950408889634f;
    float4 v = reinterpret_cast<const float4*>(x + w * DD)[lane];
    float ss = v.x * v.x + v.y * v.y + v.z * v.z + v.w * v.w;
    #pragma unroll
    for (int o = 16; o > 0; o >>= 1) ss += __shfl_xor_sync(0xFFFFFFFFu, ss, o);
    __half2* dst = reinterpret_cast<__half2*>(g_xbf + w * DD + lane * 4);
    dst[0] = __floats2half2_rn(v.x * s, v.y * s);
    dst[1] = __floats2half2_rn(v.z * s, v.w * s);
    if (lane == 0) g_ex[w] = expf(-gm * ss);
}

__global__ void prep_t_kernel(const float* __restrict__ t, const float* __restrict__ gamma,
                              const float* __restrict__ W) {
    int w = (blockIdx.x * blockDim.x + threadIdx.x) >> 5;
    int lane = threadIdx.x & 31;
    if (w >= NN) return;
    float4 v = reinterpret_cast<const float4*>(t + w * DD)[lane];
    float ss = v.x * v.x + v.y * v.y + v.z * v.z + v.w * v.w;
    #pragma unroll
    for (int o = 16; o > 0; o >>= 1) ss += __shfl_xor_sync(0xFFFFFFFFu, ss, o);
    __half2* dst = reinterpret_cast<__half2*>(g_tbf + w * DD + lane * 4);
    dst[0] = __floats2half2_rn(v.x, v.y);
    dst[1] = __floats2half2_rn(v.z, v.w);
    if (lane == 0) g_c1[w] = W[w] * expf(-gamma[0] * ss);
}

// ============================================================================
// Main kernel: 512 threads, warp grid 4m x 4n (each warp 32x32), per-nb epilogue
// ============================================================================
__global__ void __launch_bounds__(THREADS, 1)
rbf_main_kernel(const float* __restrict__ bias, float* __restrict__ out) {
    extern __shared__ char smem[];
    __shared__ int s_flag;
    uint32_t sb = smem_u32(smem);
    int tid = threadIdx.x;
    int lane = tid & 31;
    int wid = tid >> 5;
    int warp_m = wid & 3;     // 4 warps along M (32 rows each)
    int warp_n = wid >> 2;    // 4 warps along N (32 cols each)
    int g  = lane >> 2;
    int tg = lane & 3;

    int ns = blockIdx.x;
    int bt = blockIdx.y;
    int m0 = bt * BT;
    int n_base = ns * NCHUNK;

    // Prologue: A tile + B tiles 0,1 into ring slots 0,1
    issue_tile(sb + SMEM_A, g_xbf + (size_t)m0 * DD);
    issue_tile(sb + SMEM_B + 0 * TILE_BYTES, g_tbf + (size_t)n_base * DD);
    CP_COMMIT();
    issue_tile(sb + SMEM_B + 1 * TILE_BYTES, g_tbf + (size_t)(n_base + NT) * DD);
    CP_COMMIT();

    int a_row_in_warp = ((lane >> 3) & 1) * 8 + (lane & 7);
    int a_kb16 = ((lane >> 4) & 1) * 16;
    int b_row_in_nb = lane & 7;
    int b_kb16 = (lane >> 3) * 16;

    asm volatile("cp.async.wait_group 1;" ::: "memory");  // A + B0 resident
    __syncthreads();

    // Hoist A fragments (constant across the whole tile loop): 64 regs
    uint32_t af[4][2][2][4];   // [kq][ms][kk][4]
    #pragma unroll
    for (int kq = 0; kq < 4; kq++) {
        int chunk = kq >> 1;
        int kbyte0 = (kq & 1) * 64;
        uint32_t base = sb + SMEM_A + chunk * 16384;
        #pragma unroll
        for (int ms = 0; ms < 2; ms++) {
            int row = warp_m * 32 + ms * 16 + a_row_in_warp;
            ldsm4(af[kq][ms][0], base + SWZ((uint32_t)(row * 128 + kbyte0 + a_kb16)));
            ldsm4(af[kq][ms][1], base + SWZ((uint32_t)(row * 128 + kbyte0 + 32 + a_kb16)));
        }
    }

    float racc[2][2] = {{0.f, 0.f}, {0.f, 0.f}};

    for (int i = 0; i < TILES; i++) {
        asm volatile("cp.async.wait_group 1;" ::: "memory");  // tile i resident
        __syncthreads();

        // refill slot (i+2)%3 (its tile i-1 content was consumed before the sync)
        if (i + 2 < TILES)
            issue_tile(sb + SMEM_B + ((i + 2) % NBUF) * TILE_BYTES,
                       g_tbf + (size_t)(n_base + (i + 2) * NT) * DD);
        CP_COMMIT();

        uint32_t Bb = sb + SMEM_B + (i % NBUF) * TILE_BYTES;
        const float* c1base = g_c1 + n_base + i * NT + warp_n * 32;

        // This warp's 32 cols = 4 nb of 8. Per-nb: ldsm B, 16 MMAs, epilogue.
        #pragma unroll
        for (int nb = 0; nb < 4; nb++) {
            int row = warp_n * 32 + nb * 8 + b_row_in_nb;
            uint32_t bf[4][4];   // [kq][k-sub]
            #pragma unroll
            for (int kq = 0; kq < 4; kq++) {
                int chunk = kq >> 1;
                int kbyte0 = (kq & 1) * 64;
                ldsm4(bf[kq], Bb + chunk * 16384 +
                      SWZ((uint32_t)(row * 128 + kbyte0 + b_kb16)));
            }
            float acc[2][4] = {{0.f,0.f,0.f,0.f},{0.f,0.f,0.f,0.f}};
            #pragma unroll
            for (int kq = 0; kq < 4; kq++)
                #pragma unroll
                for (int kk = 0; kk < 2; kk++)
                    #pragma unroll
                    for (int ms = 0; ms < 2; ms++)
                        mma16816(acc[ms], af[kq][ms][kk], &bf[kq][kk * 2]);

            // Epilogue (ex2 + fma); cross-warp occupancy hides the acc stall.
            float2 w = *reinterpret_cast<const float2*>(c1base + nb * 8 + 2 * tg);
            #pragma unroll
            for (int ms = 0; ms < 2; ms++) {
                racc[ms][0] = fmaf(ex2f(acc[ms][0]), w.x, racc[ms][0]);
                racc[ms][0] = fmaf(ex2f(acc[ms][1]), w.y, racc[ms][0]);
                racc[ms][1] = fmaf(ex2f(acc[ms][2]), w.x, racc[ms][1]);
                racc[ms][1] = fmaf(ex2f(acc[ms][3]), w.y, racc[ms][1]);
            }
        }
    }

    // Partial write (deterministic slots; 4 col-quarters per b)
    #pragma unroll
    for (int ms = 0; ms < 2; ms++)
        #pragma unroll
        for (int h = 0; h < 2; h++) {
            float v = racc[ms][h];
            v += __shfl_xor_sync(0xFFFFFFFFu, v, 1);
            v += __shfl_xor_sync(0xFFFFFFFFu, v, 2);
            if (tg == 0) {
                int b = m0 + warp_m * 32 + ms * 16 + h * 8 + g;
                g_partial[(ns * BB + b) * 4 + warp_n] = v;
            }
        }

    // Fused reduce: last of the 8 CTAs sharing this b-tile finishes it.
    __threadfence();
    __syncthreads();
    if (tid == 0) s_flag = (atomicAdd(&g_arr[bt], 1) == NSPLITS - 1);
    __syncthreads();
    if (s_flag) {
        __threadfence();
        if (tid < BT) {
            int b = m0 + tid;
            float s = 0.0f;
            #pragma unroll
            for (int n2 = 0; n2 < NSPLITS; n2++)
                #pragma unroll
                for (int q = 0; q < 4; q++)
                    s += g_partial[(n2 * BB + b) * 4 + q];
            out[b] = fmaf(g_ex[b], s, __ldg(bias));
        }
        if (tid == 0) g_arr[bt] = 0;   // reset for next graph replay
    }
}

// ============================================================================
// Entry
// ============================================================================
extern "C" void kernel_launch(void* const* d_in, const int* in_sizes, int n_in,
                              void* d_out, int out_size) {
    const float* x     = (const float*)d_in[0];   // [2048, 128]
    const float* train = (const float*)d_in[1];   // [32768, 128]
    const float* gamma = (const float*)d_in[2];   // [1]
    const float* W     = (const float*)d_in[3];   // [1, 32768]
    const float* bias  = (const float*)d_in[4];   // [1]
    float* out = (float*)d_out;                   // [2048, 1]

    cudaFuncSetAttribute(rbf_main_kernel,
                         cudaFuncAttributeMaxDynamicSharedMemorySize, SMEM_TOTAL);

    prep_x_kernel<<<(BB * 32) / 256, 256>>>(x, gamma);
    prep_t_kernel<<<(NN * 32) / 256, 256>>>(train, gamma, W);
    rbf_main_kernel<<<dim3(NSPLITS, BTILES), THREADS, SMEM_TOTAL>>>(bias, out);
}

// round 8
// speedup vs baseline: 1.0016x; 1.0016x over previous
#include <cuda_runtime.h>
#include <cuda_fp16.h>
#include <cstdint>

// ============================================================================
// Problem constants (fixed shapes for SVMModel_19267223290147)
// ============================================================================
#define BB 2048      // batch rows
#define NN 32768     // train rows
#define DD 128       // feature dim
#define BT 128       // CTA B-tile (M)
#define NT 128       // CTA N-tile
#define NSPLITS 8    // N chunks across grid.x
#define BTILES  16   // B tiles across grid.y
#define NCHUNK (NN / NSPLITS)     // 4096
#define TILES  (NCHUNK / NT)      // 32
#define THREADS 256

// SMEM layout (dynamic): A tile + double-buffered B tiles (exact R3 layout).
#define SMEM_A  0
#define SMEM_B0 32768
#define SMEM_B1 65536
#define SMEM_TOTAL 98304

#define SWZ(o) ((o) ^ (((o) >> 3) & 0x70))

// ============================================================================
// Device globals (static allocation: allowed)
// ============================================================================
__device__ __half g_xbf[BB * DD];              // x * (2*gamma*log2e) fp16
__device__ __half g_tbf[NN * DD];              // train_data fp16
__device__ float  g_c1[NN];                    // W[n] * exp(-g*t2[n])
__device__ float  g_ex[BB];                    // exp(-g*x2[b])
__device__ float  g_partial[NSPLITS * BB * 2];
__device__ unsigned g_arr[BTILES];             // per-btile arrival counters (0-init)

// ============================================================================
// PTX helpers (sm_100 base-target safe)
// ============================================================================
__device__ __forceinline__ uint32_t smem_u32(const void* p) {
    uint32_t a;
    asm("{ .reg .u64 t; cvta.to.shared.u64 t, %1; cvt.u32.u64 %0, t; }" : "=r"(a) : "l"(p));
    return a;
}
__device__ __forceinline__ float ex2f(float x) {
    float y; asm("ex2.approx.f32 %0, %1;" : "=f"(y) : "f"(x)); return y;
}
__device__ __forceinline__ void cp_async16(uint32_t dst, const void* src) {
    asm volatile("cp.async.cg.shared.global [%0], [%1], 16;" :: "r"(dst), "l"(src));
}
#define CP_COMMIT() asm volatile("cp.async.commit_group;" ::: "memory")

__device__ __forceinline__ void ldsm4(uint32_t* r, uint32_t addr) {
    asm volatile("ldmatrix.sync.aligned.m8n8.x4.shared.b16 {%0,%1,%2,%3}, [%4];"
                 : "=r"(r[0]), "=r"(r[1]), "=r"(r[2]), "=r"(r[3]) : "r"(addr));
}
__device__ __forceinline__ void mma16816(float* c, const uint32_t* a, const uint32_t* b) {
    asm volatile(
        "mma.sync.aligned.m16n8k16.row.col.f32.f16.f16.f32 "
        "{%0,%1,%2,%3}, {%4,%5,%6,%7}, {%8,%9}, {%0,%1,%2,%3};"
        : "+f"(c[0]), "+f"(c[1]), "+f"(c[2]), "+f"(c[3])
        : "r"(a[0]), "r"(a[1]), "r"(a[2]), "r"(a[3]), "r"(b[0]), "r"(b[1]));
}

// cp.async one [128 x 128 fp16] tile into SMEM (chunked SW128 layout).
__device__ __forceinline__ void issue_tile(uint32_t sm_base, const __half* src) {
    int tid = threadIdx.x;
    #pragma unroll
    for (int it = 0; it < 8; it++) {
        int k = tid + it * 256;
        int row = k >> 4;
        int rem = k & 15;
        int c = rem >> 3;
        int j = rem & 7;
        uint32_t dst = sm_base + c * 16384 + SWZ((uint32_t)(row * 128 + j * 16));
        cp_async16(dst, src + row * 128 + c * 64 + j * 8);
    }
}

// ============================================================================
// Merged prep kernel: one warp per row; rows [0,BB) = x, rows [BB,BB+NN) = t.
// fp32 norms; x pre-scaled by 2*gamma*log2(e).
// ============================================================================
__global__ void prep_kernel(const float* __restrict__ x, const float* __restrict__ train,
                            const float* __restrict__ gamma, const float* __restrict__ W) {
    int w = (blockIdx.x * blockDim.x + threadIdx.x) >> 5;
    int lane = threadIdx.x & 31;
    float gm = gamma[0];
    if (w < BB) {
        float s = 2.0f * gm * 1.4426950408889634f;
        float4 v = reinterpret_cast<const float4*>(x + (size_t)w * DD)[lane];
        float ss = v.x * v.x + v.y * v.y + v.z * v.z + v.w * v.w;
        #pragma unroll
        for (int o = 16; o > 0; o >>= 1) ss += __shfl_xor_sync(0xFFFFFFFFu, ss, o);
        __half2* dst = reinterpret_cast<__half2*>(g_xbf + (size_t)w * DD + lane * 4);
        dst[0] = __floats2half2_rn(v.x * s, v.y * s);
        dst[1] = __floats2half2_rn(v.z * s, v.w * s);
        if (lane == 0) g_ex[w] = expf(-gm * ss);
    } else {
        int r = w - BB;
        if (r >= NN) return;
        float4 v = reinterpret_cast<const float4*>(train + (size_t)r * DD)[lane];
        float ss = v.x * v.x + v.y * v.y + v.z * v.z + v.w * v.w;
        #pragma unroll
        for (int o = 16; o > 0; o >>= 1) ss += __shfl_xor_sync(0xFFFFFFFFu, ss, o);
        __half2* dst = reinterpret_cast<__half2*>(g_tbf + (size_t)r * DD + lane * 4);
        dst[0] = __floats2half2_rn(v.x, v.y);
        dst[1] = __floats2half2_rn(v.z, v.w);
        if (lane == 0) g_c1[r] = W[r] * expf(-gm * ss);
    }
}

// ============================================================================
// Main kernel: EXACT R3 structure (256 thr, 4m x 2n warps, A hoisted,
// double-buffered B, per-nb volatile MMA + epilogue) + fused reduce tail.
// ============================================================================
__global__ void __launch_bounds__(THREADS, 1)
rbf_main_kernel(const float* __restrict__ bias, float* __restrict__ out) {
    extern __shared__ char smem[];
    __shared__ int s_flag;
    uint32_t sb = smem_u32(smem);
    int tid = threadIdx.x;
    int lane = tid & 31;
    int wid = tid >> 5;
    int warp_m = wid & 3;     // 4 warps along M (32 rows each)
    int warp_n = wid >> 2;    // 2 warps along N (64 cols each)
    int g  = lane >> 2;
    int tg = lane & 3;

    int ns = blockIdx.x;
    int bt = blockIdx.y;
    int m0 = bt * BT;
    int n_base = ns * NCHUNK;

    // Prologue: A tile + B0 (group 0), B1 (group 1)
    issue_tile(sb + SMEM_A, g_xbf + (size_t)m0 * DD);
    issue_tile(sb + SMEM_B0, g_tbf + (size_t)n_base * DD);
    CP_COMMIT();
    issue_tile(sb + SMEM_B1, g_tbf + (size_t)(n_base + NT) * DD);
    CP_COMMIT();

    int a_row_in_warp = ((lane >> 3) & 1) * 8 + (lane & 7);
    int a_kb16 = ((lane >> 4) & 1) * 16;
    int b_row_in_nb = lane & 7;
    int b_kb16 = (lane >> 3) * 16;

    asm volatile("cp.async.wait_group 1;" ::: "memory");  // A + B0 resident
    __syncthreads();

    // Hoist A fragments (constant across the whole tile loop)
    uint32_t af[4][2][2][4];   // [kq][ms][kk][4]
    #pragma unroll
    for (int kq = 0; kq < 4; kq++) {
        int chunk = kq >> 1;
        int kbyte0 = (kq & 1) * 64;
        uint32_t base = sb + SMEM_A + chunk * 16384;
        #pragma unroll
        for (int ms = 0; ms < 2; ms++) {
            int row = warp_m * 32 + ms * 16 + a_row_in_warp;
            ldsm4(af[kq][ms][0], base + SWZ((uint32_t)(row * 128 + kbyte0 + a_kb16)));
            ldsm4(af[kq][ms][1], base + SWZ((uint32_t)(row * 128 + kbyte0 + 32 + a_kb16)));
        }
    }

    float racc[2][2] = {{0.f, 0.f}, {0.f, 0.f}};

    for (int i = 0; i < TILES; i++) {
        if (i + 1 < TILES) { asm volatile("cp.async.wait_group 1;" ::: "memory"); }
        else               { asm volatile("cp.async.wait_group 0;" ::: "memory"); }
        __syncthreads();

        uint32_t Bb = sb + ((i & 1) ? SMEM_B1 : SMEM_B0);
        const float* c1base = g_c1 + n_base + i * NT + warp_n * 64;

        // Per-nb: load B frags, 16 MMAs, then immediately the exp2 epilogue.
        #pragma unroll
        for (int nb = 0; nb < 8; nb++) {
            int row = warp_n * 64 + nb * 8 + b_row_in_nb;
            uint32_t bf[4][4];   // [kq][k-sub]
            #pragma unroll
            for (int kq = 0; kq < 4; kq++) {
                int chunk = kq >> 1;
                int kbyte0 = (kq & 1) * 64;
                ldsm4(bf[kq], Bb + chunk * 16384 +
                      SWZ((uint32_t)(row * 128 + kbyte0 + b_kb16)));
            }
            float acc[2][4] = {{0.f,0.f,0.f,0.f},{0.f,0.f,0.f,0.f}};
            #pragma unroll
            for (int kq = 0; kq < 4; kq++)
                #pragma unroll
                for (int kk = 0; kk < 2; kk++)
                    #pragma unroll
                    for (int ms = 0; ms < 2; ms++)
                        mma16816(acc[ms], af[kq][ms][kk], &bf[kq][kk * 2]);

            float2 w = *reinterpret_cast<const float2*>(c1base + nb * 8 + 2 * tg);
            #pragma unroll
            for (int ms = 0; ms < 2; ms++) {
                racc[ms][0] = fmaf(ex2f(acc[ms][0]), w.x, racc[ms][0]);
                racc[ms][0] = fmaf(ex2f(acc[ms][1]), w.y, racc[ms][0]);
                racc[ms][1] = fmaf(ex2f(acc[ms][2]), w.x, racc[ms][1]);
                racc[ms][1] = fmaf(ex2f(acc[ms][3]), w.y, racc[ms][1]);
            }
        }

        __syncthreads();   // all warps done reading Bb
        if (i + 2 < TILES) {
            issue_tile(Bb, g_tbf + (size_t)(n_base + (i + 2) * NT) * DD);
            CP_COMMIT();
        }
    }

    // Partial write (deterministic slots)
    #pragma unroll
    for (int ms = 0; ms < 2; ms++)
        #pragma unroll
        for (int h = 0; h < 2; h++) {
            float v = racc[ms][h];
            v += __shfl_xor_sync(0xFFFFFFFFu, v, 1);
            v += __shfl_xor_sync(0xFFFFFFFFu, v, 2);
            if (tg == 0) {
                int b = m0 + warp_m * 32 + ms * 16 + h * 8 + g;
                g_partial[(ns * BB + b) * 2 + warp_n] = v;
            }
        }

    // Fused reduce: last of the 8 CTAs sharing this b-tile finishes it.
    __threadfence();
    __syncthreads();
    if (tid == 0) s_flag = (atomicAdd(&g_arr[bt], 1) == NSPLITS - 1);
    __syncthreads();
    if (s_flag) {
        __threadfence();
        if (tid < BT) {
            int b = m0 + tid;
            float s = 0.0f;
            #pragma unroll
            for (int n2 = 0; n2 < NSPLITS; n2++) {
                s += g_partial[(n2 * BB + b) * 2 + 0];
                s += g_partial[(n2 * BB + b) * 2 + 1];
            }
            out[b] = fmaf(g_ex[b], s, __ldg(bias));
        }
        if (tid == 0) g_arr[bt] = 0;   // reset for next graph replay
    }
}

// ============================================================================
// Entry
// ============================================================================
extern "C" void kernel_launch(void* const* d_in, const int* in_sizes, int n_in,
                              void* d_out, int out_size) {
    const float* x     = (const float*)d_in[0];   // [2048, 128]
    const float* train = (const float*)d_in[1];   // [32768, 128]
    const float* gamma = (const float*)d_in[2];   // [1]
    const float* W     = (const float*)d_in[3];   // [1, 32768]
    const float* bias  = (const float*)d_in[4];   // [1]
    float* out = (float*)d_out;                   // [2048, 1]

    cudaFuncSetAttribute(rbf_main_kernel,
                         cudaFuncAttributeMaxDynamicSharedMemorySize, SMEM_TOTAL);

    // One merged prep launch: (BB + NN) warps = 34816 -> 4352 blocks of 256.
    prep_kernel<<<((BB + NN) * 32) / 256, 256>>>(x, train, gamma, W);
    rbf_main_kernel<<<dim3(NSPLITS, BTILES), THREADS, SMEM_TOTAL>>>(bias, out);
}

// round 9
// speedup vs baseline: 1.1052x; 1.1034x over previous
#include <cuda_runtime.h>
#include <cuda_fp16.h>
#include <cstdint>

// ============================================================================
// Problem constants (fixed shapes for SVMModel_19267223290147)
// ============================================================================
#define BB 2048      // batch rows
#define NN 32768     // train rows
#define DD 128       // feature dim
#define BT 128       // CTA B-tile (M)
#define NT 128       // CTA N-tile
#define NSPLITS 8    // N chunks across grid.x
#define BTILES  16   // B tiles across grid.y
#define NCHUNK (NN / NSPLITS)     // 4096
#define TILES  (NCHUNK / NT)      // 32
#define THREADS 256

// SMEM layout (dynamic): A tile + double-buffered B tiles (exact R3 layout).
#define SMEM_A  0
#define SMEM_B0 32768
#define SMEM_B1 65536
#define SMEM_TOTAL 98304

#define SWZ(o) ((o) ^ (((o) >> 3) & 0x70))

// ============================================================================
// Device globals (static allocation: allowed)
// ============================================================================
__device__ __half g_xbf[BB * DD];              // x * (2*gamma*log2e) fp16
__device__ __half g_tbf[NN * DD];              // train_data fp16
__device__ float  g_c1[NN];                    // W[n] * exp(-g*t2[n])
__device__ float  g_ex[BB];                    // exp(-g*x2[b])
__device__ float  g_partial[NSPLITS * BB * 2];

// ============================================================================
// PTX helpers (sm_100 base-target safe)
// ============================================================================
__device__ __forceinline__ uint32_t smem_u32(const void* p) {
    uint32_t a;
    asm("{ .reg .u64 t; cvta.to.shared.u64 t, %1; cvt.u32.u64 %0, t; }" : "=r"(a) : "l"(p));
    return a;
}
__device__ __forceinline__ float ex2f(float x) {
    float y; asm("ex2.approx.f32 %0, %1;" : "=f"(y) : "f"(x)); return y;
}
__device__ __forceinline__ void cp_async16(uint32_t dst, const void* src) {
    asm volatile("cp.async.cg.shared.global [%0], [%1], 16;" :: "r"(dst), "l"(src));
}
#define CP_COMMIT() asm volatile("cp.async.commit_group;" ::: "memory")

__device__ __forceinline__ void ldsm4(uint32_t* r, uint32_t addr) {
    asm volatile("ldmatrix.sync.aligned.m8n8.x4.shared.b16 {%0,%1,%2,%3}, [%4];"
                 : "=r"(r[0]), "=r"(r[1]), "=r"(r[2]), "=r"(r[3]) : "r"(addr));
}
__device__ __forceinline__ void mma16816(float* c, const uint32_t* a, const uint32_t* b) {
    asm volatile(
        "mma.sync.aligned.m16n8k16.row.col.f32.f16.f16.f32 "
        "{%0,%1,%2,%3}, {%4,%5,%6,%7}, {%8,%9}, {%0,%1,%2,%3};"
        : "+f"(c[0]), "+f"(c[1]), "+f"(c[2]), "+f"(c[3])
        : "r"(a[0]), "r"(a[1]), "r"(a[2]), "r"(a[3]), "r"(b[0]), "r"(b[1]));
}

// cp.async one [128 x 128 fp16] tile into SMEM (chunked SW128 layout).
__device__ __forceinline__ void issue_tile(uint32_t sm_base, const __half* src) {
    int tid = threadIdx.x;
    #pragma unroll
    for (int it = 0; it < 8; it++) {
        int k = tid + it * 256;
        int row = k >> 4;
        int rem = k & 15;
        int c = rem >> 3;
        int j = rem & 7;
        uint32_t dst = sm_base + c * 16384 + SWZ((uint32_t)(row * 128 + j * 16));
        cp_async16(dst, src + row * 128 + c * 64 + j * 8);
    }
}

// ============================================================================
// Prep kernels (fp32 norms; x pre-scaled by 2*gamma*log2e) — R3 structure
// ============================================================================
__global__ void prep_x_kernel(const float* __restrict__ x, const float* __restrict__ gamma) {
    int w = (blockIdx.x * blockDim.x + threadIdx.x) >> 5;
    int lane = threadIdx.x & 31;
    if (w >= BB) return;
    float gm = gamma[0];
    float s = 2.0f * gm * 1.4426950408889634f;
    float4 v = reinterpret_cast<const float4*>(x + w * DD)[lane];
    float ss = v.x * v.x + v.y * v.y + v.z * v.z + v.w * v.w;
    #pragma unroll
    for (int o = 16; o > 0; o >>= 1) ss += __shfl_xor_sync(0xFFFFFFFFu, ss, o);
    __half2* dst = reinterpret_cast<__half2*>(g_xbf + w * DD + lane * 4);
    dst[0] = __floats2half2_rn(v.x * s, v.y * s);
    dst[1] = __floats2half2_rn(v.z * s, v.w * s);
    if (lane == 0) g_ex[w] = expf(-gm * ss);
}

__global__ void prep_t_kernel(const float* __restrict__ t, const float* __restrict__ gamma,
                              const float* __restrict__ W) {
    int w = (blockIdx.x * blockDim.x + threadIdx.x) >> 5;
    int lane = threadIdx.x & 31;
    if (w >= NN) return;
    float4 v = reinterpret_cast<const float4*>(t + w * DD)[lane];
    float ss = v.x * v.x + v.y * v.y + v.z * v.z + v.w * v.w;
    #pragma unroll
    for (int o = 16; o > 0; o >>= 1) ss += __shfl_xor_sync(0xFFFFFFFFu, ss, o);
    __half2* dst = reinterpret_cast<__half2*>(g_tbf + w * DD + lane * 4);
    dst[0] = __floats2half2_rn(v.x, v.y);
    dst[1] = __floats2half2_rn(v.z, v.w);
    if (lane == 0) g_c1[w] = W[w] * expf(-gamma[0] * ss);
}

// ============================================================================
// Main kernel: R3 structure; ONLY change = nb processed in PAIRS
// (4 independent accumulator chains, MMA dep distance 4).
// ============================================================================
__global__ void __launch_bounds__(THREADS, 1)
rbf_main_kernel() {
    extern __shared__ char smem[];
    uint32_t sb = smem_u32(smem);
    int tid = threadIdx.x;
    int lane = tid & 31;
    int wid = tid >> 5;
    int warp_m = wid & 3;     // 4 warps along M (32 rows each)
    int warp_n = wid >> 2;    // 2 warps along N (64 cols each)
    int g  = lane >> 2;
    int tg = lane & 3;

    int m0 = blockIdx.y * BT;
    int ns = blockIdx.x;
    int n_base = ns * NCHUNK;

    // Prologue: A tile + B0 (group 0), B1 (group 1)
    issue_tile(sb + SMEM_A, g_xbf + (size_t)m0 * DD);
    issue_tile(sb + SMEM_B0, g_tbf + (size_t)n_base * DD);
    CP_COMMIT();
    issue_tile(sb + SMEM_B1, g_tbf + (size_t)(n_base + NT) * DD);
    CP_COMMIT();

    int a_row_in_warp = ((lane >> 3) & 1) * 8 + (lane & 7);
    int a_kb16 = ((lane >> 4) & 1) * 16;
    int b_row_in_nb = lane & 7;
    int b_kb16 = (lane >> 3) * 16;

    asm volatile("cp.async.wait_group 1;" ::: "memory");  // A + B0 resident
    __syncthreads();

    // Hoist A fragments (constant across the whole tile loop)
    uint32_t af[4][2][2][4];   // [kq][ms][kk][4]
    #pragma unroll
    for (int kq = 0; kq < 4; kq++) {
        int chunk = kq >> 1;
        int kbyte0 = (kq & 1) * 64;
        uint32_t base = sb + SMEM_A + chunk * 16384;
        #pragma unroll
        for (int ms = 0; ms < 2; ms++) {
            int row = warp_m * 32 + ms * 16 + a_row_in_warp;
            ldsm4(af[kq][ms][0], base + SWZ((uint32_t)(row * 128 + kbyte0 + a_kb16)));
            ldsm4(af[kq][ms][1], base + SWZ((uint32_t)(row * 128 + kbyte0 + 32 + a_kb16)));
        }
    }

    float racc[2][2] = {{0.f, 0.f}, {0.f, 0.f}};

    for (int i = 0; i < TILES; i++) {
        if (i + 1 < TILES) { asm volatile("cp.async.wait_group 1;" ::: "memory"); }
        else               { asm volatile("cp.async.wait_group 0;" ::: "memory"); }
        __syncthreads();

        uint32_t Bb = sb + ((i & 1) ? SMEM_B1 : SMEM_B0);
        const float* c1base = g_c1 + n_base + i * NT + warp_n * 64;

        // nb pairs: ldsm B for both, 32 MMAs over 4 indep chains, then epilogue.
        #pragma unroll
        for (int np = 0; np < 4; np++) {
            uint32_t bf[2][4][4];   // [nb2][kq][k-sub]
            #pragma unroll
            for (int nb2 = 0; nb2 < 2; nb2++) {
                int row = warp_n * 64 + (np * 2 + nb2) * 8 + b_row_in_nb;
                #pragma unroll
                for (int kq = 0; kq < 4; kq++) {
                    int chunk = kq >> 1;
                    int kbyte0 = (kq & 1) * 64;
                    ldsm4(bf[nb2][kq], Bb + chunk * 16384 +
                          SWZ((uint32_t)(row * 128 + kbyte0 + b_kb16)));
                }
            }
            float acc[2][2][4];     // [nb2][ms][4]
            #pragma unroll
            for (int nb2 = 0; nb2 < 2; nb2++)
                #pragma unroll
                for (int ms = 0; ms < 2; ms++)
                    #pragma unroll
                    for (int c = 0; c < 4; c++) acc[nb2][ms][c] = 0.f;

            // kq -> kk -> nb2 -> ms: same-chain MMAs are 4 issues apart.
            #pragma unroll
            for (int kq = 0; kq < 4; kq++)
                #pragma unroll
                for (int kk = 0; kk < 2; kk++)
                    #pragma unroll
                    for (int nb2 = 0; nb2 < 2; nb2++)
                        #pragma unroll
                        for (int ms = 0; ms < 2; ms++)
                            mma16816(acc[nb2][ms], af[kq][ms][kk], &bf[nb2][kq][kk * 2]);

            // Epilogue for the pair (ex2 + fma)
            #pragma unroll
            for (int nb2 = 0; nb2 < 2; nb2++) {
                float2 w = *reinterpret_cast<const float2*>(
                    c1base + (np * 2 + nb2) * 8 + 2 * tg);
                #pragma unroll
                for (int ms = 0; ms < 2; ms++) {
                    racc[ms][0] = fmaf(ex2f(acc[nb2][ms][0]), w.x, racc[ms][0]);
                    racc[ms][0] = fmaf(ex2f(acc[nb2][ms][1]), w.y, racc[ms][0]);
                    racc[ms][1] = fmaf(ex2f(acc[nb2][ms][2]), w.x, racc[ms][1]);
                    racc[ms][1] = fmaf(ex2f(acc[nb2][ms][3]), w.y, racc[ms][1]);
                }
            }
        }

        __syncthreads();   // all warps done reading Bb
        if (i + 2 < TILES) {
            issue_tile(Bb, g_tbf + (size_t)(n_base + (i + 2) * NT) * DD);
            CP_COMMIT();
        }
    }

    // Reduce over the 4 lanes sharing each row, write deterministic partials.
    #pragma unroll
    for (int ms = 0; ms < 2; ms++)
        #pragma unroll
        for (int h = 0; h < 2; h++) {
            float v = racc[ms][h];
            v += __shfl_xor_sync(0xFFFFFFFFu, v, 1);
            v += __shfl_xor_sync(0xFFFFFFFFu, v, 2);
            if (tg == 0) {
                int b = m0 + warp_m * 32 + ms * 16 + h * 8 + g;
                g_partial[(ns * BB + b) * 2 + warp_n] = v;
            }
        }
}

// ============================================================================
// Final reduction: out[b] = e_x[b] * sum(partials) + bias
// ============================================================================
__global__ void reduce_kernel(const float* __restrict__ bias, float* __restrict__ out) {
    int b = blockIdx.x * blockDim.x + threadIdx.x;
    if (b >= BB) return;
    float s = 0.0f;
    #pragma unroll
    for (int ns = 0; ns < NSPLITS; ns++) {
        s += g_partial[(ns * BB + b) * 2 + 0];
        s += g_partial[(ns * BB + b) * 2 + 1];
    }
    out[b] = fmaf(g_ex[b], s, __ldg(bias));
}

// ============================================================================
// Entry — R3 launch structure (4 launches)
// ============================================================================
extern "C" void kernel_launch(void* const* d_in, const int* in_sizes, int n_in,
                              void* d_out, int out_size) {
    const float* x     = (const float*)d_in[0];   // [2048, 128]
    const float* train = (const float*)d_in[1];   // [32768, 128]
    const float* gamma = (const float*)d_in[2];   // [1]
    const float* W     = (const float*)d_in[3];   // [1, 32768]
    const float* bias  = (const float*)d_in[4];   // [1]
    float* out = (float*)d_out;                   // [2048, 1]

    cudaFuncSetAttribute(rbf_main_kernel,
                         cudaFuncAttributeMaxDynamicSharedMemorySize, SMEM_TOTAL);

    prep_x_kernel<<<(BB * 32) / THREADS, THREADS>>>(x, gamma);
    prep_t_kernel<<<(NN * 32) / THREADS, THREADS>>>(train, gamma, W);
    rbf_main_kernel<<<dim3(NSPLITS, BTILES), THREADS, SMEM_TOTAL>>>();
    reduce_kernel<<<BB / THREADS, THREADS>>>(bias, out);
}